// round 2
// baseline (speedup 1.0000x reference)
#include <cuda_runtime.h>

#define N_NODES 50000
#define N_EDGES 800000
#define IN_DIM  8
#define EDGE_DIM 4
#define HIDDEN  16

// ---------------- scratch (device globals; no allocation allowed) ----------------
__device__ float g_x1 [N_NODES * HIDDEN];   // layer-0 output (input to layer 1)
__device__ float g_agg[N_NODES * HIDDEN];   // scatter accumulator (reused per layer)
__device__ float g_cnt[N_NODES];            // in-degree counts (float)

__device__ __forceinline__ float sigmoidf_(float x) {
    return 1.0f / (1.0f + __expf(-x));
}

// ---------------- zero scratch ----------------
// grid covers exactly N_NODES*HIDDEN = 800000 with 3125x256
__global__ void zero_kernel() {
    int i = blockIdx.x * blockDim.x + threadIdx.x;
    if (i < N_NODES * HIDDEN) g_agg[i] = 0.0f;
    if (i < N_NODES)          g_cnt[i] = 0.0f;
}

// ---------------- fused per-edge kernel ----------------
// Computes: h = silu(ea @ W1 + b1)            [16]
//           Wedge[i][o] = h . W2[:, i*16+o] + b2[i*16+o]
//           msg[o] = sum_i x_src[i] * Wedge[i][o]
//           red-add msg into g_agg[dst], (layer 0 also counts degree)
// W2 is staged into shared TRANSPOSED: sW2t[(i*16+o)*16 + k] = W2[k][i*16+o]
// so the k-dot is contiguous (LDS.128, warp-uniform broadcast).
template<int DIN, bool COUNT>
__global__ void __launch_bounds__(256)
edge_kernel(const float* __restrict__ xin, const int* __restrict__ ei,
            const float* __restrict__ ea,
            const float* __restrict__ W1, const float* __restrict__ b1,
            const float* __restrict__ W2, const float* __restrict__ b2)
{
    constexpr int C = DIN * HIDDEN;          // columns of W2
    __shared__ float sW1 [EDGE_DIM * HIDDEN];
    __shared__ float sb1 [HIDDEN];
    __shared__ float sW2t[C * HIDDEN];       // transposed, k contiguous
    __shared__ float sb2 [C];

    const int tid = threadIdx.x;
    for (int t = tid; t < C * HIDDEN; t += blockDim.x) {
        int k = t & (HIDDEN - 1);
        int c = t >> 4;
        sW2t[t] = W2[k * C + c];
    }
    for (int t = tid; t < EDGE_DIM * HIDDEN; t += blockDim.x) sW1[t] = W1[t];
    if (tid < HIDDEN) sb1[tid] = b1[tid];
    for (int t = tid; t < C; t += blockDim.x) sb2[t] = b2[t];
    __syncthreads();

    const int e = blockIdx.x * blockDim.x + tid;
    if (e >= N_EDGES) return;

    const int src = ei[e];
    const int dst = ei[N_EDGES + e];

    // edge MLP hidden: h = silu(ea @ W1 + b1)
    const float4 a4 = reinterpret_cast<const float4*>(ea)[e];
    float h[HIDDEN];
#pragma unroll
    for (int j = 0; j < HIDDEN; j++) {
        float v = sb1[j]
                + a4.x * sW1[0 * HIDDEN + j]
                + a4.y * sW1[1 * HIDDEN + j]
                + a4.z * sW1[2 * HIDDEN + j]
                + a4.w * sW1[3 * HIDDEN + j];
        h[j] = v * sigmoidf_(v);
    }

    // gather source features (L2-resident)
    const float* xp = (DIN == HIDDEN) ? (const float*)g_x1 : xin;
    float xs[DIN];
    const float4* xrow = reinterpret_cast<const float4*>(xp + (size_t)src * DIN);
#pragma unroll
    for (int i4 = 0; i4 < DIN / 4; i4++) {
        float4 v = xrow[i4];
        xs[i4 * 4 + 0] = v.x; xs[i4 * 4 + 1] = v.y;
        xs[i4 * 4 + 2] = v.z; xs[i4 * 4 + 3] = v.w;
    }

    // msg[o] = sum_i x_i * (b2[i,o] + sum_k h_k * W2[k,i,o])
    float msg[HIDDEN];
#pragma unroll
    for (int o = 0; o < HIDDEN; o++) msg[o] = 0.0f;

#pragma unroll
    for (int i = 0; i < DIN; i++) {
        const float xi = xs[i];
#pragma unroll
        for (int o = 0; o < HIDDEN; o++) {
            const float* wp = &sW2t[(i * HIDDEN + o) * HIDDEN];
            float w = sb2[i * HIDDEN + o];
#pragma unroll
            for (int k = 0; k < HIDDEN; k++) w += h[k] * wp[k];
            msg[o] += xi * w;
        }
    }

    // scatter: vector reductions (no return), 4 floats per instruction
    float* base = &g_agg[(size_t)dst * HIDDEN];
#pragma unroll
    for (int o = 0; o < HIDDEN; o += 4) {
        asm volatile("red.global.add.v4.f32 [%0], {%1,%2,%3,%4};"
                     :: "l"(base + o),
                        "f"(msg[o]), "f"(msg[o + 1]), "f"(msg[o + 2]), "f"(msg[o + 3])
                     : "memory");
    }
    if (COUNT) {
        asm volatile("red.global.add.f32 [%0], %1;"
                     :: "l"(&g_cnt[dst]), "f"(1.0f) : "memory");
    }
}

// ---------------- layer-0 node update ----------------
// x1 = relu(x @ root + agg/max(cnt,1) + bias); also rezero agg for layer 1.
__global__ void __launch_bounds__(128)
node0_kernel(const float* __restrict__ x, const float* __restrict__ root,
             const float* __restrict__ bias)
{
    __shared__ float sroot[IN_DIM * HIDDEN];  // 128
    __shared__ float sbias[HIDDEN];
    const int tid = threadIdx.x;
    if (tid < IN_DIM * HIDDEN) sroot[tid] = root[tid];
    if (tid < HIDDEN)          sbias[tid] = bias[tid];
    __syncthreads();

    const int n = blockIdx.x * blockDim.x + tid;
    if (n >= N_NODES) return;

    float xs[IN_DIM];
    const float4* xr = reinterpret_cast<const float4*>(x + (size_t)n * IN_DIM);
    { float4 v = xr[0]; xs[0]=v.x; xs[1]=v.y; xs[2]=v.z; xs[3]=v.w; }
    { float4 v = xr[1]; xs[4]=v.x; xs[5]=v.y; xs[6]=v.z; xs[7]=v.w; }

    const float inv = 1.0f / fmaxf(g_cnt[n], 1.0f);
    float4* ar = reinterpret_cast<float4*>(&g_agg[(size_t)n * HIDDEN]);
    float4* x1r = reinterpret_cast<float4*>(&g_x1[(size_t)n * HIDDEN]);

    float acc[HIDDEN];
#pragma unroll
    for (int q = 0; q < 4; q++) {
        float4 a = ar[q];
        acc[q * 4 + 0] = sbias[q * 4 + 0] + a.x * inv;
        acc[q * 4 + 1] = sbias[q * 4 + 1] + a.y * inv;
        acc[q * 4 + 2] = sbias[q * 4 + 2] + a.z * inv;
        acc[q * 4 + 3] = sbias[q * 4 + 3] + a.w * inv;
    }
#pragma unroll
    for (int i = 0; i < IN_DIM; i++) {
        const float xi = xs[i];
#pragma unroll
        for (int o = 0; o < HIDDEN; o++) acc[o] += xi * sroot[i * HIDDEN + o];
    }
#pragma unroll
    for (int q = 0; q < 4; q++) {
        float4 v;
        v.x = fmaxf(acc[q * 4 + 0], 0.0f);
        v.y = fmaxf(acc[q * 4 + 1], 0.0f);
        v.z = fmaxf(acc[q * 4 + 2], 0.0f);
        v.w = fmaxf(acc[q * 4 + 3], 0.0f);
        x1r[q] = v;
        ar[q] = make_float4(0.0f, 0.0f, 0.0f, 0.0f);  // rezero for layer 1
    }
}

// ---------------- layer-1 node update + MLP head ----------------
__global__ void __launch_bounds__(128)
node1_kernel(const float* __restrict__ root, const float* __restrict__ bias,
             const float* __restrict__ mW1, const float* __restrict__ mb1,
             const float* __restrict__ mW2, const float* __restrict__ mb2,
             float* __restrict__ out)
{
    __shared__ float sroot[HIDDEN * HIDDEN];  // 256
    __shared__ float smW1 [HIDDEN * HIDDEN];  // 256
    __shared__ float smW2 [HIDDEN];
    __shared__ float sbias[HIDDEN];
    __shared__ float smb1 [HIDDEN];
    __shared__ float smb2s;

    const int tid = threadIdx.x;
    for (int t = tid; t < HIDDEN * HIDDEN; t += blockDim.x) {
        sroot[t] = root[t];
        smW1[t]  = mW1[t];
    }
    if (tid < HIDDEN) { smW2[tid] = mW2[tid]; sbias[tid] = bias[tid]; smb1[tid] = mb1[tid]; }
    if (tid == 0) smb2s = mb2[0];
    __syncthreads();

    const int n = blockIdx.x * blockDim.x + tid;
    if (n >= N_NODES) return;

    float x1v[HIDDEN];
    const float4* xr = reinterpret_cast<const float4*>(&g_x1[(size_t)n * HIDDEN]);
#pragma unroll
    for (int q = 0; q < 4; q++) {
        float4 v = xr[q];
        x1v[q * 4 + 0] = v.x; x1v[q * 4 + 1] = v.y;
        x1v[q * 4 + 2] = v.z; x1v[q * 4 + 3] = v.w;
    }
    const float inv = 1.0f / fmaxf(g_cnt[n], 1.0f);
    const float4* ar = reinterpret_cast<const float4*>(&g_agg[(size_t)n * HIDDEN]);

    float x2[HIDDEN];
#pragma unroll
    for (int q = 0; q < 4; q++) {
        float4 a = ar[q];
        x2[q * 4 + 0] = sbias[q * 4 + 0] + a.x * inv;
        x2[q * 4 + 1] = sbias[q * 4 + 1] + a.y * inv;
        x2[q * 4 + 2] = sbias[q * 4 + 2] + a.z * inv;
        x2[q * 4 + 3] = sbias[q * 4 + 3] + a.w * inv;
    }
#pragma unroll
    for (int i = 0; i < HIDDEN; i++) {
        const float xi = x1v[i];
#pragma unroll
        for (int o = 0; o < HIDDEN; o++) x2[o] += xi * sroot[i * HIDDEN + o];
    }
#pragma unroll
    for (int o = 0; o < HIDDEN; o++) x2[o] = fmaxf(x2[o], 0.0f);

    // head: silu(x2 @ mW1 + mb1) @ mW2 + mb2 -> sigmoid
    float hm[HIDDEN];
#pragma unroll
    for (int o = 0; o < HIDDEN; o++) hm[o] = smb1[o];
#pragma unroll
    for (int i = 0; i < HIDDEN; i++) {
        const float xi = x2[i];
#pragma unroll
        for (int o = 0; o < HIDDEN; o++) hm[o] += xi * smW1[i * HIDDEN + o];
    }
    float z = smb2s;
#pragma unroll
    for (int i = 0; i < HIDDEN; i++) {
        float t = hm[i];
        z += (t * sigmoidf_(t)) * smW2[i];
    }
    out[n] = sigmoidf_(z);
}

// ---------------- launch ----------------
extern "C" void kernel_launch(void* const* d_in, const int* in_sizes, int n_in,
                              void* d_out, int out_size)
{
    const float* x      = (const float*)d_in[0];
    const int*   ei     = (const int*)  d_in[1];
    const float* ea     = (const float*)d_in[2];
    const float* eW1_0  = (const float*)d_in[3];
    const float* eb1_0  = (const float*)d_in[4];
    const float* eW2_0  = (const float*)d_in[5];
    const float* eb2_0  = (const float*)d_in[6];
    const float* root_0 = (const float*)d_in[7];
    const float* bias_0 = (const float*)d_in[8];
    const float* eW1_1  = (const float*)d_in[9];
    const float* eb1_1  = (const float*)d_in[10];
    const float* eW2_1  = (const float*)d_in[11];
    const float* eb2_1  = (const float*)d_in[12];
    const float* root_1 = (const float*)d_in[13];
    const float* bias_1 = (const float*)d_in[14];
    const float* mW1    = (const float*)d_in[15];
    const float* mb1    = (const float*)d_in[16];
    const float* mW2    = (const float*)d_in[17];
    const float* mb2    = (const float*)d_in[18];
    float* out = (float*)d_out;

    const int EB = 256;
    const int EG = (N_EDGES + EB - 1) / EB;     // 3125
    const int NB = 128;
    const int NG = (N_NODES + NB - 1) / NB;     // 391

    zero_kernel<<<EG, EB>>>();
    edge_kernel<IN_DIM, true ><<<EG, EB>>>(x, ei, ea, eW1_0, eb1_0, eW2_0, eb2_0);
    node0_kernel<<<NG, NB>>>(x, root_0, bias_0);
    edge_kernel<HIDDEN, false><<<EG, EB>>>(nullptr, ei, ea, eW1_1, eb1_1, eW2_1, eb2_1);
    node1_kernel<<<NG, NB>>>(root_1, bias_1, mW1, mb1, mW2, mb2, out);
}

// round 5
// speedup vs baseline: 1.0413x; 1.0413x over previous
#include <cuda_runtime.h>

#define N_NODES 50000
#define N_EDGES 800000
#define IN_DIM  8
#define EDGE_DIM 4
#define HIDDEN  16

// ---------------- scratch (device globals; no allocation allowed) ----------------
__device__ float g_x1 [N_NODES * HIDDEN];   // layer-0 output (input to layer 1)
__device__ float g_agg[N_NODES * HIDDEN];   // scatter accumulator (reused per layer)
__device__ float g_cnt[N_NODES];            // in-degree counts (float)

__device__ __forceinline__ float sigmoidf_(float x) {
    return 1.0f / (1.0f + __expf(-x));
}

// ---------------- zero scratch ----------------
__global__ void zero_kernel() {
    int i = blockIdx.x * blockDim.x + threadIdx.x;
    if (i < N_NODES * HIDDEN) g_agg[i] = 0.0f;
    if (i < N_NODES)          g_cnt[i] = 0.0f;
}

// ---------------- fused per-edge kernel, 2 edges per thread ----------------
// h = silu(ea @ W1 + b1); Wedge[i][o] = h.W2[:,i*16+o] + b2[i*16+o]
// msg[o] = sum_i x_src[i]*Wedge[i][o]; red-add into g_agg[dst].
// W2 staged in shared TRANSPOSED (k contiguous) -> broadcast LDS.128.
// Register blocking: each LDS.128 of 4 weights feeds 8 FMAs (2 edges).
template<int DIN, bool COUNT>
__global__ void __launch_bounds__(256)
edge_kernel(const float* __restrict__ xin, const int* __restrict__ ei,
            const float* __restrict__ ea,
            const float* __restrict__ W1, const float* __restrict__ b1,
            const float* __restrict__ W2, const float* __restrict__ b2)
{
    constexpr int C = DIN * HIDDEN;          // columns of W2
    __shared__ float sW1 [EDGE_DIM * HIDDEN];
    __shared__ float sb1 [HIDDEN];
    __shared__ float sW2t[C * HIDDEN];       // transposed, k contiguous
    __shared__ float sb2 [C];

    const int tid = threadIdx.x;
    for (int t = tid; t < C * HIDDEN; t += 256) {
        int k = t & (HIDDEN - 1);
        int c = t >> 4;
        sW2t[t] = W2[k * C + c];
    }
    for (int t = tid; t < EDGE_DIM * HIDDEN; t += 256) sW1[t] = W1[t];
    if (tid < HIDDEN) sb1[tid] = b1[tid];
    for (int t = tid; t < C; t += 256) sb2[t] = b2[t];
    __syncthreads();

    const int e0 = blockIdx.x * 512 + tid;
    const int e1 = e0 + 256;
    if (e0 >= N_EDGES) return;
    const bool v1 = (e1 < N_EDGES);

    const int src0 = ei[e0];
    const int dst0 = ei[N_EDGES + e0];
    const int src1 = v1 ? ei[e1] : 0;
    const int dst1 = v1 ? ei[N_EDGES + e1] : 0;

    // edge MLP hidden for both edges
    const float4 a0 = reinterpret_cast<const float4*>(ea)[e0];
    const float4 a1 = v1 ? reinterpret_cast<const float4*>(ea)[e1]
                         : make_float4(0.f, 0.f, 0.f, 0.f);
    float h0[HIDDEN], h1[HIDDEN];
#pragma unroll
    for (int j = 0; j < HIDDEN; j++) {
        const float w0j = sW1[0 * HIDDEN + j];
        const float w1j = sW1[1 * HIDDEN + j];
        const float w2j = sW1[2 * HIDDEN + j];
        const float w3j = sW1[3 * HIDDEN + j];
        const float bj  = sb1[j];
        float u = bj + a0.x * w0j + a0.y * w1j + a0.z * w2j + a0.w * w3j;
        float v = bj + a1.x * w0j + a1.y * w1j + a1.z * w2j + a1.w * w3j;
        h0[j] = u * sigmoidf_(u);
        h1[j] = v * sigmoidf_(v);
    }

    // gather source features (L2-resident)
    const float* xp = (DIN == HIDDEN) ? (const float*)g_x1 : xin;
    float xs0[DIN], xs1[DIN];
    {
        const float4* r0 = reinterpret_cast<const float4*>(xp + (size_t)src0 * DIN);
        const float4* r1 = reinterpret_cast<const float4*>(xp + (size_t)src1 * DIN);
#pragma unroll
        for (int q = 0; q < DIN / 4; q++) {
            float4 v0 = r0[q], w1v = r1[q];
            xs0[q * 4 + 0] = v0.x; xs0[q * 4 + 1] = v0.y;
            xs0[q * 4 + 2] = v0.z; xs0[q * 4 + 3] = v0.w;
            xs1[q * 4 + 0] = w1v.x; xs1[q * 4 + 1] = w1v.y;
            xs1[q * 4 + 2] = w1v.z; xs1[q * 4 + 3] = w1v.w;
        }
    }

    float msg0[HIDDEN], msg1[HIDDEN];
#pragma unroll
    for (int o = 0; o < HIDDEN; o++) { msg0[o] = 0.0f; msg1[o] = 0.0f; }

#pragma unroll
    for (int i = 0; i < DIN; i++) {
        const float xi0 = xs0[i];
        const float xi1 = xs1[i];
#pragma unroll
        for (int o = 0; o < HIDDEN; o++) {
            const float4* wp = reinterpret_cast<const float4*>(&sW2t[(i * HIDDEN + o) * HIDDEN]);
            const float b = sb2[i * HIDDEN + o];
            float w0 = b, w1 = b;
#pragma unroll
            for (int q = 0; q < 4; q++) {
                const float4 wv = wp[q];
                w0 += h0[q * 4 + 0] * wv.x + h0[q * 4 + 1] * wv.y
                    + h0[q * 4 + 2] * wv.z + h0[q * 4 + 3] * wv.w;
                w1 += h1[q * 4 + 0] * wv.x + h1[q * 4 + 1] * wv.y
                    + h1[q * 4 + 2] * wv.z + h1[q * 4 + 3] * wv.w;
            }
            msg0[o] += xi0 * w0;
            msg1[o] += xi1 * w1;
        }
    }

    // scatter: vector reductions (no return), 4 floats per instruction
    {
        float* base = &g_agg[(size_t)dst0 * HIDDEN];
#pragma unroll
        for (int o = 0; o < HIDDEN; o += 4) {
            asm volatile("red.global.add.v4.f32 [%0], {%1,%2,%3,%4};"
                         :: "l"(base + o),
                            "f"(msg0[o]), "f"(msg0[o + 1]), "f"(msg0[o + 2]), "f"(msg0[o + 3])
                         : "memory");
        }
        if (COUNT) {
            asm volatile("red.global.add.f32 [%0], %1;"
                         :: "l"(&g_cnt[dst0]), "f"(1.0f) : "memory");
        }
    }
    if (v1) {
        float* base = &g_agg[(size_t)dst1 * HIDDEN];
#pragma unroll
        for (int o = 0; o < HIDDEN; o += 4) {
            asm volatile("red.global.add.v4.f32 [%0], {%1,%2,%3,%4};"
                         :: "l"(base + o),
                            "f"(msg1[o]), "f"(msg1[o + 1]), "f"(msg1[o + 2]), "f"(msg1[o + 3])
                         : "memory");
        }
        if (COUNT) {
            asm volatile("red.global.add.f32 [%0], %1;"
                         :: "l"(&g_cnt[dst1]), "f"(1.0f) : "memory");
        }
    }
}

// ---------------- layer-0 node update ----------------
__global__ void __launch_bounds__(128)
node0_kernel(const float* __restrict__ x, const float* __restrict__ root,
             const float* __restrict__ bias)
{
    __shared__ float sroot[IN_DIM * HIDDEN];  // 128
    __shared__ float sbias[HIDDEN];
    const int tid = threadIdx.x;
    if (tid < IN_DIM * HIDDEN) sroot[tid] = root[tid];
    if (tid < HIDDEN)          sbias[tid] = bias[tid];
    __syncthreads();

    const int n = blockIdx.x * blockDim.x + tid;
    if (n >= N_NODES) return;

    float xs[IN_DIM];
    const float4* xr = reinterpret_cast<const float4*>(x + (size_t)n * IN_DIM);
    { float4 v = xr[0]; xs[0]=v.x; xs[1]=v.y; xs[2]=v.z; xs[3]=v.w; }
    { float4 v = xr[1]; xs[4]=v.x; xs[5]=v.y; xs[6]=v.z; xs[7]=v.w; }

    const float inv = 1.0f / fmaxf(g_cnt[n], 1.0f);
    float4* ar = reinterpret_cast<float4*>(&g_agg[(size_t)n * HIDDEN]);
    float4* x1r = reinterpret_cast<float4*>(&g_x1[(size_t)n * HIDDEN]);

    float acc[HIDDEN];
#pragma unroll
    for (int q = 0; q < 4; q++) {
        float4 a = ar[q];
        acc[q * 4 + 0] = sbias[q * 4 + 0] + a.x * inv;
        acc[q * 4 + 1] = sbias[q * 4 + 1] + a.y * inv;
        acc[q * 4 + 2] = sbias[q * 4 + 2] + a.z * inv;
        acc[q * 4 + 3] = sbias[q * 4 + 3] + a.w * inv;
    }
#pragma unroll
    for (int i = 0; i < IN_DIM; i++) {
        const float xi = xs[i];
#pragma unroll
        for (int o = 0; o < HIDDEN; o++) acc[o] += xi * sroot[i * HIDDEN + o];
    }
#pragma unroll
    for (int q = 0; q < 4; q++) {
        float4 v;
        v.x = fmaxf(acc[q * 4 + 0], 0.0f);
        v.y = fmaxf(acc[q * 4 + 1], 0.0f);
        v.z = fmaxf(acc[q * 4 + 2], 0.0f);
        v.w = fmaxf(acc[q * 4 + 3], 0.0f);
        x1r[q] = v;
        ar[q] = make_float4(0.0f, 0.0f, 0.0f, 0.0f);  // rezero for layer 1
    }
}

// ---------------- layer-1 node update + MLP head ----------------
__global__ void __launch_bounds__(128)
node1_kernel(const float* __restrict__ root, const float* __restrict__ bias,
             const float* __restrict__ mW1, const float* __restrict__ mb1,
             const float* __restrict__ mW2, const float* __restrict__ mb2,
             float* __restrict__ out)
{
    __shared__ float sroot[HIDDEN * HIDDEN];  // 256
    __shared__ float smW1 [HIDDEN * HIDDEN];  // 256
    __shared__ float smW2 [HIDDEN];
    __shared__ float sbias[HIDDEN];
    __shared__ float smb1 [HIDDEN];
    __shared__ float smb2s;

    const int tid = threadIdx.x;
    for (int t = tid; t < HIDDEN * HIDDEN; t += blockDim.x) {
        sroot[t] = root[t];
        smW1[t]  = mW1[t];
    }
    if (tid < HIDDEN) { smW2[tid] = mW2[tid]; sbias[tid] = bias[tid]; smb1[tid] = mb1[tid]; }
    if (tid == 0) smb2s = mb2[0];
    __syncthreads();

    const int n = blockIdx.x * blockDim.x + tid;
    if (n >= N_NODES) return;

    float x1v[HIDDEN];
    const float4* xr = reinterpret_cast<const float4*>(&g_x1[(size_t)n * HIDDEN]);
#pragma unroll
    for (int q = 0; q < 4; q++) {
        float4 v = xr[q];
        x1v[q * 4 + 0] = v.x; x1v[q * 4 + 1] = v.y;
        x1v[q * 4 + 2] = v.z; x1v[q * 4 + 3] = v.w;
    }
    const float inv = 1.0f / fmaxf(g_cnt[n], 1.0f);
    const float4* ar = reinterpret_cast<const float4*>(&g_agg[(size_t)n * HIDDEN]);

    float x2[HIDDEN];
#pragma unroll
    for (int q = 0; q < 4; q++) {
        float4 a = ar[q];
        x2[q * 4 + 0] = sbias[q * 4 + 0] + a.x * inv;
        x2[q * 4 + 1] = sbias[q * 4 + 1] + a.y * inv;
        x2[q * 4 + 2] = sbias[q * 4 + 2] + a.z * inv;
        x2[q * 4 + 3] = sbias[q * 4 + 3] + a.w * inv;
    }
#pragma unroll
    for (int i = 0; i < HIDDEN; i++) {
        const float xi = x1v[i];
#pragma unroll
        for (int o = 0; o < HIDDEN; o++) x2[o] += xi * sroot[i * HIDDEN + o];
    }
#pragma unroll
    for (int o = 0; o < HIDDEN; o++) x2[o] = fmaxf(x2[o], 0.0f);

    // head: silu(x2 @ mW1 + mb1) @ mW2 + mb2 -> sigmoid
    float hm[HIDDEN];
#pragma unroll
    for (int o = 0; o < HIDDEN; o++) hm[o] = smb1[o];
#pragma unroll
    for (int i = 0; i < HIDDEN; i++) {
        const float xi = x2[i];
#pragma unroll
        for (int o = 0; o < HIDDEN; o++) hm[o] += xi * smW1[i * HIDDEN + o];
    }
    float z = smb2s;
#pragma unroll
    for (int i = 0; i < HIDDEN; i++) {
        float t = hm[i];
        z += (t * sigmoidf_(t)) * smW2[i];
    }
    out[n] = sigmoidf_(z);
}

// ---------------- launch ----------------
extern "C" void kernel_launch(void* const* d_in, const int* in_sizes, int n_in,
                              void* d_out, int out_size)
{
    const float* x      = (const float*)d_in[0];
    const int*   ei     = (const int*)  d_in[1];
    const float* ea     = (const float*)d_in[2];
    const float* eW1_0  = (const float*)d_in[3];
    const float* eb1_0  = (const float*)d_in[4];
    const float* eW2_0  = (const float*)d_in[5];
    const float* eb2_0  = (const float*)d_in[6];
    const float* root_0 = (const float*)d_in[7];
    const float* bias_0 = (const float*)d_in[8];
    const float* eW1_1  = (const float*)d_in[9];
    const float* eb1_1  = (const float*)d_in[10];
    const float* eW2_1  = (const float*)d_in[11];
    const float* eb2_1  = (const float*)d_in[12];
    const float* root_1 = (const float*)d_in[13];
    const float* bias_1 = (const float*)d_in[14];
    const float* mW1    = (const float*)d_in[15];
    const float* mb1    = (const float*)d_in[16];
    const float* mW2    = (const float*)d_in[17];
    const float* mb2    = (const float*)d_in[18];
    float* out = (float*)d_out;

    const int ZB = 256;
    const int ZG = (N_NODES * HIDDEN + ZB - 1) / ZB;   // 3125
    const int EB = 256;
    const int EG = (N_EDGES + EB * 2 - 1) / (EB * 2);  // 1563
    const int NB = 128;
    const int NG = (N_NODES + NB - 1) / NB;            // 391

    zero_kernel<<<ZG, ZB>>>();
    edge_kernel<IN_DIM, true ><<<EG, EB>>>(x, ei, ea, eW1_0, eb1_0, eW2_0, eb2_0);
    node0_kernel<<<NG, NB>>>(x, root_0, bias_0);
    edge_kernel<HIDDEN, false><<<EG, EB>>>(nullptr, ei, ea, eW1_1, eb1_1, eW2_1, eb2_1);
    node1_kernel<<<NG, NB>>>(root_1, bias_1, mW1, mb1, mW2, mb2, out);
}

// round 6
// speedup vs baseline: 1.1860x; 1.1390x over previous
#include <cuda_runtime.h>

#define N_NODES 50000
#define N_EDGES 800000
#define IN_DIM  8
#define EDGE_DIM 4
#define HIDDEN  16

// ---------------- scratch (device globals; no allocation allowed) ----------------
__device__ float g_x1 [N_NODES * HIDDEN];   // layer-0 output (input to layer 1)
__device__ float g_agg[N_NODES * HIDDEN];   // scatter accumulator (reused per layer)
__device__ float g_cnt[N_NODES];            // in-degree counts (float)

__device__ __forceinline__ float sigmoidf_(float x) {
    return 1.0f / (1.0f + __expf(-x));
}

// ---------------- packed f32x2 helpers ----------------
__device__ __forceinline__ unsigned long long pk2(float lo, float hi) {
    unsigned long long r;
    asm("mov.b64 %0, {%1, %2};" : "=l"(r) : "f"(lo), "f"(hi));
    return r;
}
__device__ __forceinline__ unsigned long long fma2(unsigned long long a,
                                                   unsigned long long b,
                                                   unsigned long long c) {
    unsigned long long d;
    asm("fma.rn.f32x2 %0, %1, %2, %3;" : "=l"(d) : "l"(a), "l"(b), "l"(c));
    return d;
}
__device__ __forceinline__ float hsum2(unsigned long long p) {
    float lo, hi;
    asm("mov.b64 {%0, %1}, %2;" : "=f"(lo), "=f"(hi) : "l"(p));
    return lo + hi;
}
__device__ __forceinline__ void lds_v2u64(unsigned long long& a, unsigned long long& b,
                                          unsigned addr) {
    asm volatile("ld.shared.v2.u64 {%0, %1}, [%2];" : "=l"(a), "=l"(b) : "r"(addr));
}
__device__ __forceinline__ unsigned long long lds_u64(unsigned addr) {
    unsigned long long a;
    asm volatile("ld.shared.u64 %0, [%1];" : "=l"(a) : "r"(addr));
    return a;
}

// ---------------- zero scratch ----------------
__global__ void zero_kernel() {
    int i = blockIdx.x * blockDim.x + threadIdx.x;
    if (i < N_NODES * HIDDEN) g_agg[i] = 0.0f;
    if (i < N_NODES)          g_cnt[i] = 0.0f;
}

// ---------------- fused per-edge kernel, 2 edges/thread, packed f32x2 k-dot ----
// h = silu(ea @ W1 + b1); Wedge[i][o] = h . W2[:,i*16+o] + b2[i*16+o]
// msg[o] = sum_i x_src[i]*Wedge[i][o]; red-add into g_agg[dst].
// W2 staged in shared TRANSPOSED (k contiguous); rows loaded as b64 pairs and
// the k-dot runs as packed fma.rn.f32x2 (2 MACs per fma-pipe op).
template<int DIN, bool COUNT>
__global__ void __launch_bounds__(256)
edge_kernel(const float* __restrict__ xin, const int* __restrict__ ei,
            const float* __restrict__ ea,
            const float* __restrict__ W1, const float* __restrict__ b1,
            const float* __restrict__ W2, const float* __restrict__ b2)
{
    constexpr int C = DIN * HIDDEN;          // columns of W2
    __shared__ __align__(16) float  sW1 [EDGE_DIM * HIDDEN];
    __shared__ float                sb1 [HIDDEN];
    __shared__ __align__(16) float  sW2t[C * HIDDEN];   // transposed, k contiguous
    __shared__ __align__(8)  float2 sb2p[C];            // {b2, 0}

    const int tid = threadIdx.x;
    for (int t = tid; t < C * HIDDEN; t += 256) {
        int k = t & (HIDDEN - 1);
        int c = t >> 4;
        sW2t[t] = W2[k * C + c];
    }
    for (int t = tid; t < EDGE_DIM * HIDDEN; t += 256) sW1[t] = W1[t];
    if (tid < HIDDEN) sb1[tid] = b1[tid];
    for (int t = tid; t < C; t += 256) sb2p[t] = make_float2(b2[t], 0.0f);
    __syncthreads();

    const unsigned sw2_base = (unsigned)__cvta_generic_to_shared(sW2t);
    const unsigned sb2_base = (unsigned)__cvta_generic_to_shared(sb2p);

    const int e0 = blockIdx.x * 512 + tid;
    const int e1 = e0 + 256;
    if (e0 >= N_EDGES) return;
    const bool v1 = (e1 < N_EDGES);

    const int src0 = ei[e0];
    const int dst0 = ei[N_EDGES + e0];
    const int src1 = v1 ? ei[e1] : 0;
    const int dst1 = v1 ? ei[N_EDGES + e1] : 0;

    // edge MLP hidden for both edges, packed into f32x2 pairs over k
    const float4 a0 = reinterpret_cast<const float4*>(ea)[e0];
    const float4 a1 = v1 ? reinterpret_cast<const float4*>(ea)[e1]
                         : make_float4(0.f, 0.f, 0.f, 0.f);
    unsigned long long hp0[HIDDEN / 2], hp1[HIDDEN / 2];
#pragma unroll
    for (int j2 = 0; j2 < HIDDEN / 2; j2++) {
        float hv0[2], hv1[2];
#pragma unroll
        for (int s = 0; s < 2; s++) {
            const int j = j2 * 2 + s;
            const float w0j = sW1[0 * HIDDEN + j];
            const float w1j = sW1[1 * HIDDEN + j];
            const float w2j = sW1[2 * HIDDEN + j];
            const float w3j = sW1[3 * HIDDEN + j];
            const float bj  = sb1[j];
            float u = bj + a0.x * w0j + a0.y * w1j + a0.z * w2j + a0.w * w3j;
            float v = bj + a1.x * w0j + a1.y * w1j + a1.z * w2j + a1.w * w3j;
            hv0[s] = u * sigmoidf_(u);
            hv1[s] = v * sigmoidf_(v);
        }
        hp0[j2] = pk2(hv0[0], hv0[1]);
        hp1[j2] = pk2(hv1[0], hv1[1]);
    }

    // gather source features (L2-resident)
    const float* xp = (DIN == HIDDEN) ? (const float*)g_x1 : xin;
    float xs0[DIN], xs1[DIN];
    {
        const float4* r0 = reinterpret_cast<const float4*>(xp + (size_t)src0 * DIN);
        const float4* r1 = reinterpret_cast<const float4*>(xp + (size_t)src1 * DIN);
#pragma unroll
        for (int q = 0; q < DIN / 4; q++) {
            float4 v0 = r0[q], w1v = r1[q];
            xs0[q * 4 + 0] = v0.x; xs0[q * 4 + 1] = v0.y;
            xs0[q * 4 + 2] = v0.z; xs0[q * 4 + 3] = v0.w;
            xs1[q * 4 + 0] = w1v.x; xs1[q * 4 + 1] = w1v.y;
            xs1[q * 4 + 2] = w1v.z; xs1[q * 4 + 3] = w1v.w;
        }
    }

    float msg0[HIDDEN], msg1[HIDDEN];
#pragma unroll
    for (int o = 0; o < HIDDEN; o++) { msg0[o] = 0.0f; msg1[o] = 0.0f; }

#pragma unroll
    for (int i = 0; i < DIN; i++) {
        const float xi0 = xs0[i];
        const float xi1 = xs1[i];
#pragma unroll
        for (int o = 0; o < HIDDEN; o++) {
            const int c = i * HIDDEN + o;
            const unsigned waddr = sw2_base + (unsigned)(c * (HIDDEN * 4));
            unsigned long long wa, wb, wc, wd, we, wf, wg, wh;
            lds_v2u64(wa, wb, waddr);
            lds_v2u64(wc, wd, waddr + 16);
            lds_v2u64(we, wf, waddr + 32);
            lds_v2u64(wg, wh, waddr + 48);
            const unsigned long long binit = lds_u64(sb2_base + (unsigned)(c * 8));

            unsigned long long acc0 = binit;
            acc0 = fma2(hp0[0], wa, acc0);
            acc0 = fma2(hp0[1], wb, acc0);
            acc0 = fma2(hp0[2], wc, acc0);
            acc0 = fma2(hp0[3], wd, acc0);
            acc0 = fma2(hp0[4], we, acc0);
            acc0 = fma2(hp0[5], wf, acc0);
            acc0 = fma2(hp0[6], wg, acc0);
            acc0 = fma2(hp0[7], wh, acc0);
            msg0[o] += xi0 * hsum2(acc0);

            unsigned long long acc1 = binit;
            acc1 = fma2(hp1[0], wa, acc1);
            acc1 = fma2(hp1[1], wb, acc1);
            acc1 = fma2(hp1[2], wc, acc1);
            acc1 = fma2(hp1[3], wd, acc1);
            acc1 = fma2(hp1[4], we, acc1);
            acc1 = fma2(hp1[5], wf, acc1);
            acc1 = fma2(hp1[6], wg, acc1);
            acc1 = fma2(hp1[7], wh, acc1);
            msg1[o] += xi1 * hsum2(acc1);
        }
    }

    // scatter: vector reductions (no return), 4 floats per instruction
    {
        float* base = &g_agg[(size_t)dst0 * HIDDEN];
#pragma unroll
        for (int o = 0; o < HIDDEN; o += 4) {
            asm volatile("red.global.add.v4.f32 [%0], {%1,%2,%3,%4};"
                         :: "l"(base + o),
                            "f"(msg0[o]), "f"(msg0[o + 1]), "f"(msg0[o + 2]), "f"(msg0[o + 3])
                         : "memory");
        }
        if (COUNT) {
            asm volatile("red.global.add.f32 [%0], %1;"
                         :: "l"(&g_cnt[dst0]), "f"(1.0f) : "memory");
        }
    }
    if (v1) {
        float* base = &g_agg[(size_t)dst1 * HIDDEN];
#pragma unroll
        for (int o = 0; o < HIDDEN; o += 4) {
            asm volatile("red.global.add.v4.f32 [%0], {%1,%2,%3,%4};"
                         :: "l"(base + o),
                            "f"(msg1[o]), "f"(msg1[o + 1]), "f"(msg1[o + 2]), "f"(msg1[o + 3])
                         : "memory");
        }
        if (COUNT) {
            asm volatile("red.global.add.f32 [%0], %1;"
                         :: "l"(&g_cnt[dst1]), "f"(1.0f) : "memory");
        }
    }
}

// ---------------- layer-0 node update ----------------
__global__ void __launch_bounds__(128)
node0_kernel(const float* __restrict__ x, const float* __restrict__ root,
             const float* __restrict__ bias)
{
    __shared__ float sroot[IN_DIM * HIDDEN];  // 128
    __shared__ float sbias[HIDDEN];
    const int tid = threadIdx.x;
    if (tid < IN_DIM * HIDDEN) sroot[tid] = root[tid];
    if (tid < HIDDEN)          sbias[tid] = bias[tid];
    __syncthreads();

    const int n = blockIdx.x * blockDim.x + tid;
    if (n >= N_NODES) return;

    float xs[IN_DIM];
    const float4* xr = reinterpret_cast<const float4*>(x + (size_t)n * IN_DIM);
    { float4 v = xr[0]; xs[0]=v.x; xs[1]=v.y; xs[2]=v.z; xs[3]=v.w; }
    { float4 v = xr[1]; xs[4]=v.x; xs[5]=v.y; xs[6]=v.z; xs[7]=v.w; }

    const float inv = 1.0f / fmaxf(g_cnt[n], 1.0f);
    float4* ar = reinterpret_cast<float4*>(&g_agg[(size_t)n * HIDDEN]);
    float4* x1r = reinterpret_cast<float4*>(&g_x1[(size_t)n * HIDDEN]);

    float acc[HIDDEN];
#pragma unroll
    for (int q = 0; q < 4; q++) {
        float4 a = ar[q];
        acc[q * 4 + 0] = sbias[q * 4 + 0] + a.x * inv;
        acc[q * 4 + 1] = sbias[q * 4 + 1] + a.y * inv;
        acc[q * 4 + 2] = sbias[q * 4 + 2] + a.z * inv;
        acc[q * 4 + 3] = sbias[q * 4 + 3] + a.w * inv;
    }
#pragma unroll
    for (int i = 0; i < IN_DIM; i++) {
        const float xi = xs[i];
#pragma unroll
        for (int o = 0; o < HIDDEN; o++) acc[o] += xi * sroot[i * HIDDEN + o];
    }
#pragma unroll
    for (int q = 0; q < 4; q++) {
        float4 v;
        v.x = fmaxf(acc[q * 4 + 0], 0.0f);
        v.y = fmaxf(acc[q * 4 + 1], 0.0f);
        v.z = fmaxf(acc[q * 4 + 2], 0.0f);
        v.w = fmaxf(acc[q * 4 + 3], 0.0f);
        x1r[q] = v;
        ar[q] = make_float4(0.0f, 0.0f, 0.0f, 0.0f);  // rezero for layer 1
    }
}

// ---------------- layer-1 node update + MLP head ----------------
__global__ void __launch_bounds__(128)
node1_kernel(const float* __restrict__ root, const float* __restrict__ bias,
             const float* __restrict__ mW1, const float* __restrict__ mb1,
             const float* __restrict__ mW2, const float* __restrict__ mb2,
             float* __restrict__ out)
{
    __shared__ float sroot[HIDDEN * HIDDEN];  // 256
    __shared__ float smW1 [HIDDEN * HIDDEN];  // 256
    __shared__ float smW2 [HIDDEN];
    __shared__ float sbias[HIDDEN];
    __shared__ float smb1 [HIDDEN];
    __shared__ float smb2s;

    const int tid = threadIdx.x;
    for (int t = tid; t < HIDDEN * HIDDEN; t += blockDim.x) {
        sroot[t] = root[t];
        smW1[t]  = mW1[t];
    }
    if (tid < HIDDEN) { smW2[tid] = mW2[tid]; sbias[tid] = bias[tid]; smb1[tid] = mb1[tid]; }
    if (tid == 0) smb2s = mb2[0];
    __syncthreads();

    const int n = blockIdx.x * blockDim.x + tid;
    if (n >= N_NODES) return;

    float x1v[HIDDEN];
    const float4* xr = reinterpret_cast<const float4*>(&g_x1[(size_t)n * HIDDEN]);
#pragma unroll
    for (int q = 0; q < 4; q++) {
        float4 v = xr[q];
        x1v[q * 4 + 0] = v.x; x1v[q * 4 + 1] = v.y;
        x1v[q * 4 + 2] = v.z; x1v[q * 4 + 3] = v.w;
    }
    const float inv = 1.0f / fmaxf(g_cnt[n], 1.0f);
    const float4* ar = reinterpret_cast<const float4*>(&g_agg[(size_t)n * HIDDEN]);

    float x2[HIDDEN];
#pragma unroll
    for (int q = 0; q < 4; q++) {
        float4 a = ar[q];
        x2[q * 4 + 0] = sbias[q * 4 + 0] + a.x * inv;
        x2[q * 4 + 1] = sbias[q * 4 + 1] + a.y * inv;
        x2[q * 4 + 2] = sbias[q * 4 + 2] + a.z * inv;
        x2[q * 4 + 3] = sbias[q * 4 + 3] + a.w * inv;
    }
#pragma unroll
    for (int i = 0; i < HIDDEN; i++) {
        const float xi = x1v[i];
#pragma unroll
        for (int o = 0; o < HIDDEN; o++) x2[o] += xi * sroot[i * HIDDEN + o];
    }
#pragma unroll
    for (int o = 0; o < HIDDEN; o++) x2[o] = fmaxf(x2[o], 0.0f);

    // head: silu(x2 @ mW1 + mb1) @ mW2 + mb2 -> sigmoid
    float hm[HIDDEN];
#pragma unroll
    for (int o = 0; o < HIDDEN; o++) hm[o] = smb1[o];
#pragma unroll
    for (int i = 0; i < HIDDEN; i++) {
        const float xi = x2[i];
#pragma unroll
        for (int o = 0; o < HIDDEN; o++) hm[o] += xi * smW1[i * HIDDEN + o];
    }
    float z = smb2s;
#pragma unroll
    for (int i = 0; i < HIDDEN; i++) {
        float t = hm[i];
        z += (t * sigmoidf_(t)) * smW2[i];
    }
    out[n] = sigmoidf_(z);
}

// ---------------- launch ----------------
extern "C" void kernel_launch(void* const* d_in, const int* in_sizes, int n_in,
                              void* d_out, int out_size)
{
    const float* x      = (const float*)d_in[0];
    const int*   ei     = (const int*)  d_in[1];
    const float* ea     = (const float*)d_in[2];
    const float* eW1_0  = (const float*)d_in[3];
    const float* eb1_0  = (const float*)d_in[4];
    const float* eW2_0  = (const float*)d_in[5];
    const float* eb2_0  = (const float*)d_in[6];
    const float* root_0 = (const float*)d_in[7];
    const float* bias_0 = (const float*)d_in[8];
    const float* eW1_1  = (const float*)d_in[9];
    const float* eb1_1  = (const float*)d_in[10];
    const float* eW2_1  = (const float*)d_in[11];
    const float* eb2_1  = (const float*)d_in[12];
    const float* root_1 = (const float*)d_in[13];
    const float* bias_1 = (const float*)d_in[14];
    const float* mW1    = (const float*)d_in[15];
    const float* mb1    = (const float*)d_in[16];
    const float* mW2    = (const float*)d_in[17];
    const float* mb2    = (const float*)d_in[18];
    float* out = (float*)d_out;

    const int ZB = 256;
    const int ZG = (N_NODES * HIDDEN + ZB - 1) / ZB;   // 3125
    const int EB = 256;
    const int EG = (N_EDGES + EB * 2 - 1) / (EB * 2);  // 1563
    const int NB = 128;
    const int NG = (N_NODES + NB - 1) / NB;            // 391

    zero_kernel<<<ZG, ZB>>>();
    edge_kernel<IN_DIM, true ><<<EG, EB>>>(x, ei, ea, eW1_0, eb1_0, eW2_0, eb2_0);
    node0_kernel<<<NG, NB>>>(x, root_0, bias_0);
    edge_kernel<HIDDEN, false><<<EG, EB>>>(nullptr, ei, ea, eW1_1, eb1_1, eW2_1, eb2_1);
    node1_kernel<<<NG, NB>>>(root_1, bias_1, mW1, mb1, mW2, mb2, out);
}

// round 9
// speedup vs baseline: 1.2653x; 1.0668x over previous
#include <cuda_runtime.h>

#define N_NODES 50000
#define N_EDGES 800000
#define IN_DIM  8
#define EDGE_DIM 4
#define HIDDEN  16

// ---------------- scratch (device globals; no allocation allowed) ----------------
__device__ float g_x1 [N_NODES * HIDDEN];   // layer-0 output (input to layer 1)
__device__ float g_agg[N_NODES * HIDDEN];   // scatter accumulator (reused per layer)
__device__ float g_cnt[N_NODES];            // in-degree counts (float)

__device__ __forceinline__ float sigmoidf_(float x) {
    return 1.0f / (1.0f + __expf(-x));
}

// ---------------- packed f32x2 helpers ----------------
__device__ __forceinline__ unsigned long long pk2(float lo, float hi) {
    unsigned long long r;
    asm("mov.b64 %0, {%1, %2};" : "=l"(r) : "f"(lo), "f"(hi));
    return r;
}
__device__ __forceinline__ unsigned long long fma2(unsigned long long a,
                                                   unsigned long long b,
                                                   unsigned long long c) {
    unsigned long long d;
    asm("fma.rn.f32x2 %0, %1, %2, %3;" : "=l"(d) : "l"(a), "l"(b), "l"(c));
    return d;
}
__device__ __forceinline__ float hsum2(unsigned long long p) {
    float lo, hi;
    asm("mov.b64 {%0, %1}, %2;" : "=f"(lo), "=f"(hi) : "l"(p));
    return lo + hi;
}
__device__ __forceinline__ void lds_v2u64(unsigned long long& a, unsigned long long& b,
                                          unsigned addr) {
    asm volatile("ld.shared.v2.u64 {%0, %1}, [%2];" : "=l"(a), "=l"(b) : "r"(addr));
}
__device__ __forceinline__ unsigned long long lds_u64(unsigned addr) {
    unsigned long long a;
    asm volatile("ld.shared.u64 %0, [%1];" : "=l"(a) : "r"(addr));
    return a;
}

// ---------------- zero scratch ----------------
__global__ void zero_kernel() {
    int i = blockIdx.x * blockDim.x + threadIdx.x;
    if (i < N_NODES * HIDDEN) g_agg[i] = 0.0f;
    if (i < N_NODES)          g_cnt[i] = 0.0f;
}

// ---------------- fused per-edge kernel, 2 edges/thread, packed f32x2 k-dot ----
// h = silu(ea @ W1 + b1); Wedge[i][o] = h . W2[:,i*16+o] + b2[i*16+o]
// msg[o] = sum_i x_src[i]*Wedge[i][o]; red-add into g_agg[dst].
// W2 staged in shared TRANSPOSED (k contiguous); rows loaded as b64 pairs and
// the k-dot runs as packed fma.rn.f32x2 (2 MACs per fma-pipe op).
// i-loop chunked (4 i per chunk, outer loop NOT unrolled) so the x gather
// lives in 8 registers instead of 32 -> 2 CTAs/SM.
template<int DIN, bool COUNT>
__global__ void __launch_bounds__(256, 2)
edge_kernel(const float* __restrict__ xin, const int* __restrict__ ei,
            const float* __restrict__ ea,
            const float* __restrict__ W1, const float* __restrict__ b1,
            const float* __restrict__ W2, const float* __restrict__ b2)
{
    constexpr int C = DIN * HIDDEN;          // columns of W2
    __shared__ __align__(16) float  sW1 [EDGE_DIM * HIDDEN];
    __shared__ float                sb1 [HIDDEN];
    __shared__ __align__(16) float  sW2t[C * HIDDEN];   // transposed, k contiguous
    __shared__ __align__(8)  float2 sb2p[C];            // {b2, 0}

    const int tid = threadIdx.x;
    for (int t = tid; t < C * HIDDEN; t += 256) {
        int k = t & (HIDDEN - 1);
        int c = t >> 4;
        sW2t[t] = W2[k * C + c];
    }
    for (int t = tid; t < EDGE_DIM * HIDDEN; t += 256) sW1[t] = W1[t];
    if (tid < HIDDEN) sb1[tid] = b1[tid];
    for (int t = tid; t < C; t += 256) sb2p[t] = make_float2(b2[t], 0.0f);
    __syncthreads();

    const unsigned sw2_base = (unsigned)__cvta_generic_to_shared(sW2t);
    const unsigned sb2_base = (unsigned)__cvta_generic_to_shared(sb2p);

    const int e0 = blockIdx.x * 512 + tid;
    const int e1 = e0 + 256;
    if (e0 >= N_EDGES) return;
    const bool v1 = (e1 < N_EDGES);

    const int src0 = ei[e0];
    const int dst0 = ei[N_EDGES + e0];
    const int src1 = v1 ? ei[e1] : 0;
    const int dst1 = v1 ? ei[N_EDGES + e1] : 0;

    // edge MLP hidden for both edges, packed into f32x2 pairs over k
    const float4 a0 = reinterpret_cast<const float4*>(ea)[e0];
    const float4 a1 = v1 ? reinterpret_cast<const float4*>(ea)[e1]
                         : make_float4(0.f, 0.f, 0.f, 0.f);
    unsigned long long hp0[HIDDEN / 2], hp1[HIDDEN / 2];
#pragma unroll
    for (int j2 = 0; j2 < HIDDEN / 2; j2++) {
        float hv0[2], hv1[2];
#pragma unroll
        for (int s = 0; s < 2; s++) {
            const int j = j2 * 2 + s;
            const float w0j = sW1[0 * HIDDEN + j];
            const float w1j = sW1[1 * HIDDEN + j];
            const float w2j = sW1[2 * HIDDEN + j];
            const float w3j = sW1[3 * HIDDEN + j];
            const float bj  = sb1[j];
            float u = bj + a0.x * w0j + a0.y * w1j + a0.z * w2j + a0.w * w3j;
            float v = bj + a1.x * w0j + a1.y * w1j + a1.z * w2j + a1.w * w3j;
            hv0[s] = u * sigmoidf_(u);
            hv1[s] = v * sigmoidf_(v);
        }
        hp0[j2] = pk2(hv0[0], hv0[1]);
        hp1[j2] = pk2(hv1[0], hv1[1]);
    }

    // source feature row pointers (L2-resident)
    const float* xp = (DIN == HIDDEN) ? (const float*)g_x1 : xin;
    const float4* xr0 = reinterpret_cast<const float4*>(xp + (size_t)src0 * DIN);
    const float4* xr1 = reinterpret_cast<const float4*>(xp + (size_t)src1 * DIN);

    float msg0[HIDDEN], msg1[HIDDEN];
#pragma unroll
    for (int o = 0; o < HIDDEN; o++) { msg0[o] = 0.0f; msg1[o] = 0.0f; }

    // i-loop in chunks of 4; outer loop intentionally NOT unrolled so the
    // x gathers stay chunk-local (8 regs) instead of fully hoisted (32 regs).
#pragma unroll 1
    for (int q = 0; q < DIN / 4; q++) {
        const float4 xc0 = xr0[q];
        const float4 xc1 = xr1[q];
        const float xs0[4] = {xc0.x, xc0.y, xc0.z, xc0.w};
        const float xs1[4] = {xc1.x, xc1.y, xc1.z, xc1.w};
#pragma unroll
        for (int ii = 0; ii < 4; ii++) {
            const int i = q * 4 + ii;
            const float xi0 = xs0[ii];
            const float xi1 = xs1[ii];
#pragma unroll
            for (int o = 0; o < HIDDEN; o++) {
                const int c = i * HIDDEN + o;
                const unsigned waddr = sw2_base + (unsigned)(c * (HIDDEN * 4));
                unsigned long long wa, wb, wc, wd, we, wf, wg, wh;
                lds_v2u64(wa, wb, waddr);
                lds_v2u64(wc, wd, waddr + 16);
                lds_v2u64(we, wf, waddr + 32);
                lds_v2u64(wg, wh, waddr + 48);
                const unsigned long long binit = lds_u64(sb2_base + (unsigned)(c * 8));

                unsigned long long acc0 = binit;
                acc0 = fma2(hp0[0], wa, acc0);
                acc0 = fma2(hp0[1], wb, acc0);
                acc0 = fma2(hp0[2], wc, acc0);
                acc0 = fma2(hp0[3], wd, acc0);
                acc0 = fma2(hp0[4], we, acc0);
                acc0 = fma2(hp0[5], wf, acc0);
                acc0 = fma2(hp0[6], wg, acc0);
                acc0 = fma2(hp0[7], wh, acc0);
                msg0[o] += xi0 * hsum2(acc0);

                unsigned long long acc1 = binit;
                acc1 = fma2(hp1[0], wa, acc1);
                acc1 = fma2(hp1[1], wb, acc1);
                acc1 = fma2(hp1[2], wc, acc1);
                acc1 = fma2(hp1[3], wd, acc1);
                acc1 = fma2(hp1[4], we, acc1);
                acc1 = fma2(hp1[5], wf, acc1);
                acc1 = fma2(hp1[6], wg, acc1);
                acc1 = fma2(hp1[7], wh, acc1);
                msg1[o] += xi1 * hsum2(acc1);
            }
        }
    }

    // scatter: vector reductions (no return), 4 floats per instruction
    {
        float* base = &g_agg[(size_t)dst0 * HIDDEN];
#pragma unroll
        for (int o = 0; o < HIDDEN; o += 4) {
            asm volatile("red.global.add.v4.f32 [%0], {%1,%2,%3,%4};"
                         :: "l"(base + o),
                            "f"(msg0[o]), "f"(msg0[o + 1]), "f"(msg0[o + 2]), "f"(msg0[o + 3])
                         : "memory");
        }
        if (COUNT) {
            asm volatile("red.global.add.f32 [%0], %1;"
                         :: "l"(&g_cnt[dst0]), "f"(1.0f) : "memory");
        }
    }
    if (v1) {
        float* base = &g_agg[(size_t)dst1 * HIDDEN];
#pragma unroll
        for (int o = 0; o < HIDDEN; o += 4) {
            asm volatile("red.global.add.v4.f32 [%0], {%1,%2,%3,%4};"
                         :: "l"(base + o),
                            "f"(msg1[o]), "f"(msg1[o + 1]), "f"(msg1[o + 2]), "f"(msg1[o + 3])
                         : "memory");
        }
        if (COUNT) {
            asm volatile("red.global.add.f32 [%0], %1;"
                         :: "l"(&g_cnt[dst1]), "f"(1.0f) : "memory");
        }
    }
}

// ---------------- layer-0 node update ----------------
__global__ void __launch_bounds__(128)
node0_kernel(const float* __restrict__ x, const float* __restrict__ root,
             const float* __restrict__ bias)
{
    __shared__ float sroot[IN_DIM * HIDDEN];  // 128
    __shared__ float sbias[HIDDEN];
    const int tid = threadIdx.x;
    if (tid < IN_DIM * HIDDEN) sroot[tid] = root[tid];
    if (tid < HIDDEN)          sbias[tid] = bias[tid];
    __syncthreads();

    const int n = blockIdx.x * blockDim.x + tid;
    if (n >= N_NODES) return;

    float xs[IN_DIM];
    const float4* xr = reinterpret_cast<const float4*>(x + (size_t)n * IN_DIM);
    { float4 v = xr[0]; xs[0]=v.x; xs[1]=v.y; xs[2]=v.z; xs[3]=v.w; }
    { float4 v = xr[1]; xs[4]=v.x; xs[5]=v.y; xs[6]=v.z; xs[7]=v.w; }

    const float inv = 1.0f / fmaxf(g_cnt[n], 1.0f);
    float4* ar = reinterpret_cast<float4*>(&g_agg[(size_t)n * HIDDEN]);
    float4* x1r = reinterpret_cast<float4*>(&g_x1[(size_t)n * HIDDEN]);

    float acc[HIDDEN];
#pragma unroll
    for (int q = 0; q < 4; q++) {
        float4 a = ar[q];
        acc[q * 4 + 0] = sbias[q * 4 + 0] + a.x * inv;
        acc[q * 4 + 1] = sbias[q * 4 + 1] + a.y * inv;
        acc[q * 4 + 2] = sbias[q * 4 + 2] + a.z * inv;
        acc[q * 4 + 3] = sbias[q * 4 + 3] + a.w * inv;
    }
#pragma unroll
    for (int i = 0; i < IN_DIM; i++) {
        const float xi = xs[i];
#pragma unroll
        for (int o = 0; o < HIDDEN; o++) acc[o] += xi * sroot[i * HIDDEN + o];
    }
#pragma unroll
    for (int q = 0; q < 4; q++) {
        float4 v;
        v.x = fmaxf(acc[q * 4 + 0], 0.0f);
        v.y = fmaxf(acc[q * 4 + 1], 0.0f);
        v.z = fmaxf(acc[q * 4 + 2], 0.0f);
        v.w = fmaxf(acc[q * 4 + 3], 0.0f);
        x1r[q] = v;
        ar[q] = make_float4(0.0f, 0.0f, 0.0f, 0.0f);  // rezero for layer 1
    }
}

// ---------------- layer-1 node update + MLP head ----------------
__global__ void __launch_bounds__(128)
node1_kernel(const float* __restrict__ root, const float* __restrict__ bias,
             const float* __restrict__ mW1, const float* __restrict__ mb1,
             const float* __restrict__ mW2, const float* __restrict__ mb2,
             float* __restrict__ out)
{
    __shared__ float sroot[HIDDEN * HIDDEN];  // 256
    __shared__ float smW1 [HIDDEN * HIDDEN];  // 256
    __shared__ float smW2 [HIDDEN];
    __shared__ float sbias[HIDDEN];
    __shared__ float smb1 [HIDDEN];
    __shared__ float smb2s;

    const int tid = threadIdx.x;
    for (int t = tid; t < HIDDEN * HIDDEN; t += blockDim.x) {
        sroot[t] = root[t];
        smW1[t]  = mW1[t];
    }
    if (tid < HIDDEN) { smW2[tid] = mW2[tid]; sbias[tid] = bias[tid]; smb1[tid] = mb1[tid]; }
    if (tid == 0) smb2s = mb2[0];
    __syncthreads();

    const int n = blockIdx.x * blockDim.x + tid;
    if (n >= N_NODES) return;

    float x1v[HIDDEN];
    const float4* xr = reinterpret_cast<const float4*>(&g_x1[(size_t)n * HIDDEN]);
#pragma unroll
    for (int q = 0; q < 4; q++) {
        float4 v = xr[q];
        x1v[q * 4 + 0] = v.x; x1v[q * 4 + 1] = v.y;
        x1v[q * 4 + 2] = v.z; x1v[q * 4 + 3] = v.w;
    }
    const float inv = 1.0f / fmaxf(g_cnt[n], 1.0f);
    const float4* ar = reinterpret_cast<const float4*>(&g_agg[(size_t)n * HIDDEN]);

    float x2[HIDDEN];
#pragma unroll
    for (int q = 0; q < 4; q++) {
        float4 a = ar[q];
        x2[q * 4 + 0] = sbias[q * 4 + 0] + a.x * inv;
        x2[q * 4 + 1] = sbias[q * 4 + 1] + a.y * inv;
        x2[q * 4 + 2] = sbias[q * 4 + 2] + a.z * inv;
        x2[q * 4 + 3] = sbias[q * 4 + 3] + a.w * inv;
    }
#pragma unroll
    for (int i = 0; i < HIDDEN; i++) {
        const float xi = x1v[i];
#pragma unroll
        for (int o = 0; o < HIDDEN; o++) x2[o] += xi * sroot[i * HIDDEN + o];
    }
#pragma unroll
    for (int o = 0; o < HIDDEN; o++) x2[o] = fmaxf(x2[o], 0.0f);

    // head: silu(x2 @ mW1 + mb1) @ mW2 + mb2 -> sigmoid
    float hm[HIDDEN];
#pragma unroll
    for (int o = 0; o < HIDDEN; o++) hm[o] = smb1[o];
#pragma unroll
    for (int i = 0; i < HIDDEN; i++) {
        const float xi = x2[i];
#pragma unroll
        for (int o = 0; o < HIDDEN; o++) hm[o] += xi * smW1[i * HIDDEN + o];
    }
    float z = smb2s;
#pragma unroll
    for (int i = 0; i < HIDDEN; i++) {
        float t = hm[i];
        z += (t * sigmoidf_(t)) * smW2[i];
    }
    out[n] = sigmoidf_(z);
}

// ---------------- launch ----------------
extern "C" void kernel_launch(void* const* d_in, const int* in_sizes, int n_in,
                              void* d_out, int out_size)
{
    const float* x      = (const float*)d_in[0];
    const int*   ei     = (const int*)  d_in[1];
    const float* ea     = (const float*)d_in[2];
    const float* eW1_0  = (const float*)d_in[3];
    const float* eb1_0  = (const float*)d_in[4];
    const float* eW2_0  = (const float*)d_in[5];
    const float* eb2_0  = (const float*)d_in[6];
    const float* root_0 = (const float*)d_in[7];
    const float* bias_0 = (const float*)d_in[8];
    const float* eW1_1  = (const float*)d_in[9];
    const float* eb1_1  = (const float*)d_in[10];
    const float* eW2_1  = (const float*)d_in[11];
    const float* eb2_1  = (const float*)d_in[12];
    const float* root_1 = (const float*)d_in[13];
    const float* bias_1 = (const float*)d_in[14];
    const float* mW1    = (const float*)d_in[15];
    const float* mb1    = (const float*)d_in[16];
    const float* mW2    = (const float*)d_in[17];
    const float* mb2    = (const float*)d_in[18];
    float* out = (float*)d_out;

    const int ZB = 256;
    const int ZG = (N_NODES * HIDDEN + ZB - 1) / ZB;   // 3125
    const int EB = 256;
    const int EG = (N_EDGES + EB * 2 - 1) / (EB * 2);  // 1563
    const int NB = 128;
    const int NG = (N_NODES + NB - 1) / NB;            // 391

    zero_kernel<<<ZG, ZB>>>();
    edge_kernel<IN_DIM, true ><<<EG, EB>>>(x, ei, ea, eW1_0, eb1_0, eW2_0, eb2_0);
    node0_kernel<<<NG, NB>>>(x, root_0, bias_0);
    edge_kernel<HIDDEN, false><<<EG, EB>>>(nullptr, ei, ea, eW1_1, eb1_1, eW2_1, eb2_1);
    node1_kernel<<<NG, NB>>>(root_1, bias_1, mW1, mb1, mW2, mb2, out);
}

// round 12
// speedup vs baseline: 1.6049x; 1.2684x over previous
#include <cuda_runtime.h>
#include <cstdint>

#define N_NODES 50000
#define N_EDGES 800000
#define IN_DIM  8
#define EDGE_DIM 4
#define HIDDEN  16

// ---------------- scratch (device globals; no allocation allowed) ----------------
__device__ float g_x1 [N_NODES * HIDDEN];    // layer-0 output
__device__ float g_agg[N_NODES * HIDDEN];    // scatter accumulator
__device__ float g_cnt[N_NODES];             // in-degree counts
__device__ float g_Y  [N_NODES * HIDDEN * HIDDEN];  // per-node contracted weights [n][k][o]
__device__ float g_B  [N_NODES * HIDDEN];           // per-node contracted bias    [n][o]

__device__ __forceinline__ float sigmoidf_(float x) {
    return 1.0f / (1.0f + __expf(-x));
}

// ---------------- zero scratch ----------------
__global__ void zero_kernel() {
    int i = blockIdx.x * blockDim.x + threadIdx.x;
    if (i < N_NODES * HIDDEN) g_agg[i] = 0.0f;
    if (i < N_NODES)          g_cnt[i] = 0.0f;
}

// ---------------- Y precompute ----------------
// Y[n,k,o] = sum_i x[n,i] * W2[k, i*16+o];  B[n,o] = sum_i x[n,i] * b2[i*16+o]
// 16 threads per node (one per k), 16 nodes per block (256 threads).
template<int DIN>
__global__ void __launch_bounds__(256)
y_kernel(const float* __restrict__ xin,
         const float* __restrict__ W2, const float* __restrict__ b2)
{
    constexpr int C = DIN * HIDDEN;
    constexpr int PAD = 4;                       // 2-way max LDS conflict
    __shared__ float sW2[HIDDEN][C + PAD];
    __shared__ float sb2[C];

    const int tid = threadIdx.x;
    for (int t = tid; t < HIDDEN * C; t += 256) sW2[t / C][t % C] = W2[t];
    for (int t = tid; t < C; t += 256)          sb2[t] = b2[t];
    __syncthreads();

    const int local = tid >> 4;                  // node within block
    const int k     = tid & 15;
    const int n     = blockIdx.x * 16 + local;   // 3125 * 16 = 50000 exact

    const float* xp = (DIN == HIDDEN) ? (const float*)g_x1 : xin;
    float xs[DIN];
    {
        const float4* xr = reinterpret_cast<const float4*>(xp + (size_t)n * DIN);
#pragma unroll
        for (int q = 0; q < DIN / 4; q++) {
            float4 v = xr[q];
            xs[q * 4 + 0] = v.x; xs[q * 4 + 1] = v.y;
            xs[q * 4 + 2] = v.z; xs[q * 4 + 3] = v.w;
        }
    }

    float acc[HIDDEN];
#pragma unroll
    for (int o = 0; o < HIDDEN; o++) acc[o] = 0.0f;
#pragma unroll
    for (int i = 0; i < DIN; i++) {
        const float xi = xs[i];
#pragma unroll
        for (int o = 0; o < HIDDEN; o++) acc[o] += xi * sW2[k][i * HIDDEN + o];
    }
    float4* yw = reinterpret_cast<float4*>(&g_Y[(size_t)n * 256 + k * HIDDEN]);
#pragma unroll
    for (int q = 0; q < 4; q++)
        yw[q] = make_float4(acc[q * 4 + 0], acc[q * 4 + 1], acc[q * 4 + 2], acc[q * 4 + 3]);

    if (k == 0) {
        float bacc[HIDDEN];
#pragma unroll
        for (int o = 0; o < HIDDEN; o++) bacc[o] = 0.0f;
#pragma unroll
        for (int i = 0; i < DIN; i++) {
            const float xi = xs[i];
#pragma unroll
            for (int o = 0; o < HIDDEN; o++) bacc[o] += xi * sb2[i * HIDDEN + o];
        }
        float4* bw = reinterpret_cast<float4*>(&g_B[(size_t)n * HIDDEN]);
#pragma unroll
        for (int q = 0; q < 4; q++)
            bw[q] = make_float4(bacc[q * 4 + 0], bacc[q * 4 + 1], bacc[q * 4 + 2], bacc[q * 4 + 3]);
    }
}

// ---------------- edge kernel (Y-factorized) ----------------
// 4 lanes per edge; lane r owns o-quad [4r, 4r+4).
// h = silu(ea @ W1 + b1) staged in smem (each lane computes its own 4 j's).
// msg[o] = B[src,o] + sum_k h_k * Y[src,k,o]; red-add into g_agg[dst].
template<bool COUNT>
__global__ void __launch_bounds__(256)
edge_y_kernel(const int* __restrict__ ei, const float* __restrict__ ea,
              const float* __restrict__ W1, const float* __restrict__ b1)
{
    __shared__ float sW1[EDGE_DIM * HIDDEN];
    __shared__ float sb1[HIDDEN];
    __shared__ float sh[64][HIDDEN + 1];         // 17-float rows: conflict-free

    const int tid = threadIdx.x;
    if (tid < EDGE_DIM * HIDDEN) sW1[tid] = W1[tid];
    if (tid < HIDDEN)            sb1[tid] = b1[tid];
    __syncthreads();

    const int el = tid >> 2;                     // edge within block (0..63)
    const int r  = tid & 3;                      // o-quad index
    const int e  = blockIdx.x * 64 + el;         // 12500 * 64 = 800000 exact

    // ---- phase 1: h (each lane computes 4 of the 16 j's) ----
    const float4 a4 = reinterpret_cast<const float4*>(ea)[e];
#pragma unroll
    for (int jj = 0; jj < 4; jj++) {
        const int j = r * 4 + jj;
        float v = sb1[j] + a4.x * sW1[j] + a4.y * sW1[HIDDEN + j]
                         + a4.z * sW1[2 * HIDDEN + j] + a4.w * sW1[3 * HIDDEN + j];
        sh[el][j] = v * sigmoidf_(v);
    }
    __syncwarp();                                // writers/readers are the same warp

    // ---- phase 2: msg quad from Y (L2-resident gather) ----
    const int src = ei[e];
    const int dst = ei[N_EDGES + e];

    const float* yrow = &g_Y[(size_t)src * 256 + r * 4];
    float4 m = *reinterpret_cast<const float4*>(&g_B[(size_t)src * HIDDEN + r * 4]);

#pragma unroll
    for (int k = 0; k < HIDDEN; k++) {
        const float hk = sh[el][k];
        const float4 w = *reinterpret_cast<const float4*>(yrow + k * HIDDEN);
        m.x += hk * w.x;
        m.y += hk * w.y;
        m.z += hk * w.z;
        m.w += hk * w.w;
    }

    float* base = &g_agg[(size_t)dst * HIDDEN + r * 4];
    asm volatile("red.global.add.v4.f32 [%0], {%1,%2,%3,%4};"
                 :: "l"(base), "f"(m.x), "f"(m.y), "f"(m.z), "f"(m.w)
                 : "memory");
    if (COUNT && r == 0) {
        asm volatile("red.global.add.f32 [%0], %1;"
                     :: "l"(&g_cnt[dst]), "f"(1.0f) : "memory");
    }
}

// ---------------- layer-0 node update ----------------
__global__ void __launch_bounds__(128)
node0_kernel(const float* __restrict__ x, const float* __restrict__ root,
             const float* __restrict__ bias)
{
    __shared__ float sroot[IN_DIM * HIDDEN];
    __shared__ float sbias[HIDDEN];
    const int tid = threadIdx.x;
    if (tid < IN_DIM * HIDDEN) sroot[tid] = root[tid];
    if (tid < HIDDEN)          sbias[tid] = bias[tid];
    __syncthreads();

    const int n = blockIdx.x * blockDim.x + tid;
    if (n >= N_NODES) return;

    float xs[IN_DIM];
    const float4* xr = reinterpret_cast<const float4*>(x + (size_t)n * IN_DIM);
    { float4 v = xr[0]; xs[0]=v.x; xs[1]=v.y; xs[2]=v.z; xs[3]=v.w; }
    { float4 v = xr[1]; xs[4]=v.x; xs[5]=v.y; xs[6]=v.z; xs[7]=v.w; }

    const float inv = 1.0f / fmaxf(g_cnt[n], 1.0f);
    float4* ar  = reinterpret_cast<float4*>(&g_agg[(size_t)n * HIDDEN]);
    float4* x1r = reinterpret_cast<float4*>(&g_x1[(size_t)n * HIDDEN]);

    float acc[HIDDEN];
#pragma unroll
    for (int q = 0; q < 4; q++) {
        float4 a = ar[q];
        acc[q * 4 + 0] = sbias[q * 4 + 0] + a.x * inv;
        acc[q * 4 + 1] = sbias[q * 4 + 1] + a.y * inv;
        acc[q * 4 + 2] = sbias[q * 4 + 2] + a.z * inv;
        acc[q * 4 + 3] = sbias[q * 4 + 3] + a.w * inv;
    }
#pragma unroll
    for (int i = 0; i < IN_DIM; i++) {
        const float xi = xs[i];
#pragma unroll
        for (int o = 0; o < HIDDEN; o++) acc[o] += xi * sroot[i * HIDDEN + o];
    }
#pragma unroll
    for (int q = 0; q < 4; q++) {
        float4 v;
        v.x = fmaxf(acc[q * 4 + 0], 0.0f);
        v.y = fmaxf(acc[q * 4 + 1], 0.0f);
        v.z = fmaxf(acc[q * 4 + 2], 0.0f);
        v.w = fmaxf(acc[q * 4 + 3], 0.0f);
        x1r[q] = v;
        ar[q] = make_float4(0.0f, 0.0f, 0.0f, 0.0f);   // rezero for layer 1
    }
}

// ---------------- layer-1 node update + MLP head ----------------
__global__ void __launch_bounds__(128)
node1_kernel(const float* __restrict__ root, const float* __restrict__ bias,
             const float* __restrict__ mW1, const float* __restrict__ mb1,
             const float* __restrict__ mW2, const float* __restrict__ mb2,
             float* __restrict__ out)
{
    __shared__ float sroot[HIDDEN * HIDDEN];
    __shared__ float smW1 [HIDDEN * HIDDEN];
    __shared__ float smW2 [HIDDEN];
    __shared__ float sbias[HIDDEN];
    __shared__ float smb1 [HIDDEN];
    __shared__ float smb2s;

    const int tid = threadIdx.x;
    for (int t = tid; t < HIDDEN * HIDDEN; t += blockDim.x) {
        sroot[t] = root[t];
        smW1[t]  = mW1[t];
    }
    if (tid < HIDDEN) { smW2[tid] = mW2[tid]; sbias[tid] = bias[tid]; smb1[tid] = mb1[tid]; }
    if (tid == 0) smb2s = mb2[0];
    __syncthreads();

    const int n = blockIdx.x * blockDim.x + tid;
    if (n >= N_NODES) return;

    float x1v[HIDDEN];
    const float4* xr = reinterpret_cast<const float4*>(&g_x1[(size_t)n * HIDDEN]);
#pragma unroll
    for (int q = 0; q < 4; q++) {
        float4 v = xr[q];
        x1v[q * 4 + 0] = v.x; x1v[q * 4 + 1] = v.y;
        x1v[q * 4 + 2] = v.z; x1v[q * 4 + 3] = v.w;
    }
    const float inv = 1.0f / fmaxf(g_cnt[n], 1.0f);
    const float4* ar = reinterpret_cast<const float4*>(&g_agg[(size_t)n * HIDDEN]);

    float x2[HIDDEN];
#pragma unroll
    for (int q = 0; q < 4; q++) {
        float4 a = ar[q];
        x2[q * 4 + 0] = sbias[q * 4 + 0] + a.x * inv;
        x2[q * 4 + 1] = sbias[q * 4 + 1] + a.y * inv;
        x2[q * 4 + 2] = sbias[q * 4 + 2] + a.z * inv;
        x2[q * 4 + 3] = sbias[q * 4 + 3] + a.w * inv;
    }
#pragma unroll
    for (int i = 0; i < HIDDEN; i++) {
        const float xi = x1v[i];
#pragma unroll
        for (int o = 0; o < HIDDEN; o++) x2[o] += xi * sroot[i * HIDDEN + o];
    }
#pragma unroll
    for (int o = 0; o < HIDDEN; o++) x2[o] = fmaxf(x2[o], 0.0f);

    float hm[HIDDEN];
#pragma unroll
    for (int o = 0; o < HIDDEN; o++) hm[o] = smb1[o];
#pragma unroll
    for (int i = 0; i < HIDDEN; i++) {
        const float xi = x2[i];
#pragma unroll
        for (int o = 0; o < HIDDEN; o++) hm[o] += xi * smW1[i * HIDDEN + o];
    }
    float z = smb2s;
#pragma unroll
    for (int i = 0; i < HIDDEN; i++) {
        float t = hm[i];
        z += (t * sigmoidf_(t)) * smW2[i];
    }
    out[n] = sigmoidf_(z);
}

// ---------------- launch ----------------
extern "C" void kernel_launch(void* const* d_in, const int* in_sizes, int n_in,
                              void* d_out, int out_size)
{
    const float* x      = (const float*)d_in[0];
    const int*   ei     = (const int*)  d_in[1];
    const float* ea     = (const float*)d_in[2];
    const float* eW1_0  = (const float*)d_in[3];
    const float* eb1_0  = (const float*)d_in[4];
    const float* eW2_0  = (const float*)d_in[5];
    const float* eb2_0  = (const float*)d_in[6];
    const float* root_0 = (const float*)d_in[7];
    const float* bias_0 = (const float*)d_in[8];
    const float* eW1_1  = (const float*)d_in[9];
    const float* eb1_1  = (const float*)d_in[10];
    const float* eW2_1  = (const float*)d_in[11];
    const float* eb2_1  = (const float*)d_in[12];
    const float* root_1 = (const float*)d_in[13];
    const float* bias_1 = (const float*)d_in[14];
    const float* mW1    = (const float*)d_in[15];
    const float* mb1    = (const float*)d_in[16];
    const float* mW2    = (const float*)d_in[17];
    const float* mb2    = (const float*)d_in[18];
    float* out = (float*)d_out;

    const int ZB = 256;
    const int ZG = (N_NODES * HIDDEN + ZB - 1) / ZB;   // 3125
    const int YG = N_NODES / 16;                       // 3125 exact
    const int EG = N_EDGES * 4 / 256;                  // 12500 exact
    const int NB = 128;
    const int NG = (N_NODES + NB - 1) / NB;            // 391

    zero_kernel<<<ZG, ZB>>>();
    y_kernel<IN_DIM><<<YG, 256>>>(x, eW2_0, eb2_0);
    edge_y_kernel<true ><<<EG, 256>>>(ei, ea, eW1_0, eb1_0);
    node0_kernel<<<NG, NB>>>(x, root_0, bias_0);
    y_kernel<HIDDEN><<<YG, 256>>>(nullptr, eW2_1, eb2_1);
    edge_y_kernel<false><<<EG, 256>>>(ei, ea, eW1_1, eb1_1);
    node1_kernel<<<NG, NB>>>(root_1, bias_1, mW1, mb1, mW2, mb2, out);
}